// round 16
// baseline (speedup 1.0000x reference)
#include <cuda_runtime.h>
#include <cuda_bf16.h>
#include <cstdint>

#define MAXN 50000
#define MAXE 800000
#define Hd   64
#define MAXK 16
#define NTGT (2 + MAXK)
#define NBLK 592        // 4 blocks/SM x 148 SMs: co-resident up to 64 regs/thr

// ---------------- device scratch (no allocs allowed) ----------------
// INVARIANT: g_bitmap all-zero and g_ns1 == g_ne2 == 0 at every
// kernel_launch entry (zero-init at load; cleanup phase restores it).
static __device__ float    g_agg1[(size_t)MAXN * Hd];
static __device__ float    g_h1[(size_t)MAXN * Hd];
static __device__ float    g_h2[NTGT * Hd];
static __device__ unsigned g_bitmap[(MAXN + 31) / 32];
static __device__ int      g_s1[MAXN];
static __device__ int      g_ns1;
static __device__ int      g_e2src[MAXE];
static __device__ int      g_e2slot[MAXE];
static __device__ float    g_e2a[MAXE];
static __device__ int      g_ne2;

// grid barrier (sense-reversing; gen monotonic across calls, count self-resets)
static __device__ volatile unsigned g_gen;
static __device__ unsigned g_count;

__device__ __forceinline__ void grid_barrier() {
    __syncthreads();
    if (threadIdx.x == 0) {
        __threadfence();
        unsigned old = g_gen;
        if (atomicAdd(&g_count, 1) + 1 == gridDim.x) {
            g_count = 0;
            __threadfence();
            atomicExch((unsigned*)&g_gen, old + 1);
        } else {
            while (g_gen == old) __nanosleep(64);
        }
        __threadfence();
    }
    __syncthreads();
}

__device__ __forceinline__ void zero_agg1_row(int node) {
    float4* p = (float4*)(g_agg1 + (size_t)node * Hd);
    #pragma unroll
    for (int i = 0; i < 16; i++) p[i] = make_float4(0.f, 0.f, 0.f, 0.f);
}

__device__ __forceinline__ int sniff_is64(const void* ei, int E, long long N) {
    const long long* p = (const long long*)ei;
    int n = E < 8 ? E : 8;
    int ok = 1;
    for (int q = 0; q < n; q++) {
        long long v = p[q];
        if (v < 0 || v >= N) { ok = 0; break; }
    }
    return ok;
}

__device__ __forceinline__ int load_idx(const void* p, int i, int is64) {
    return is64 ? (int)((const long long*)p)[i] : ((const int*)p)[i];
}

// load 4 dst values starting at edge 'base' (base aligned by 4 when possible)
__device__ __forceinline__ void load_dv4(const void* ei, int E, int base,
                                         int is64, int* dv) {
    if (base + 4 <= E) {
        if (is64) {
            const long long* p = (const long long*)ei + E + base;
            longlong2 a = *(const longlong2*)p;
            longlong2 c = *(const longlong2*)(p + 2);
            dv[0] = (int)a.x; dv[1] = (int)a.y; dv[2] = (int)c.x; dv[3] = (int)c.y;
        } else {
            int4 a = *(const int4*)((const int*)ei + E + base);
            dv[0] = a.x; dv[1] = a.y; dv[2] = a.z; dv[3] = a.w;
        }
    } else {
        for (int j = 0; j < 4; j++)
            dv[j] = (base + j < E) ? load_idx(ei, E + base + j, is64) : -1;
    }
}

// ================= the whole problem, one co-resident launch ================
__global__ void __launch_bounds__(256, 4) k_all(
        const float* __restrict__ x, const void* __restrict__ ei,
        const float* __restrict__ ea,
        const void* __restrict__ curr, const void* __restrict__ dest,
        const void* __restrict__ nbr,
        const float* __restrict__ We1, const float* __restrict__ be1,
        const float* __restrict__ W1a, const float* __restrict__ b1a,
        const float* __restrict__ W1b, const float* __restrict__ b1b,
        const float* __restrict__ We2, const float* __restrict__ be2,
        const float* __restrict__ W2a, const float* __restrict__ b2a,
        const float* __restrict__ W2b, const float* __restrict__ b2b,
        const float* __restrict__ Wl1, const float* __restrict__ bl1,
        const float* __restrict__ Wl2, const float* __restrict__ bl2,
        float* __restrict__ out, int E, long long N, int K) {
    __shared__ __align__(16) float sIn[4 * Hd];
    __shared__ __align__(16) float sMu[4 * Hd];
    __shared__ __align__(16) float sA[Hd];
    __shared__ __align__(16) float sU[Hd];
    __shared__ __align__(16) float sC[3 * Hd];
    __shared__ __align__(16) float sZ[Hd];
    __shared__ int tg[NTGT];
    __shared__ int s_is64;

    int tid  = threadIdx.x;
    int bid  = blockIdx.x;
    int lane = tid & 31;
    int nt   = 2 + K;

    // ---- phase 0: per-block setup ----
    if (tid == 0) s_is64 = sniff_is64(ei, E, N);
    __syncthreads();
    int is64 = s_is64;

    if (tid < NTGT) {
        int v = -1;
        if (tid == 0)      v = load_idx(curr, 0, is64);
        else if (tid == 1) v = load_idx(dest, 0, is64);
        else if (tid < 2 + K) v = load_idx(nbr, tid - 2, is64);
        tg[tid] = v;
    }
    __syncthreads();

    if (bid == 0 && tid < 2 + K) {
        int v = tg[tid];
        unsigned bit = 1u << (v & 31);
        unsigned old = atomicOr(&g_bitmap[v >> 5], bit);
        if (!(old & bit)) {
            int sl = atomicAdd(&g_ns1, 1);
            g_s1[sl] = v;
            zero_agg1_row(v);
        }
    }

    int gwarp  = (bid * 256 + tid) >> 5;
    int nwarps = (NBLK * 256) >> 5;   // 4736 warps; 4736*128 covers E in 2 iters

    // ---- phase A: target hits -> e2 payload + S1 growth ----
    for (int wb = gwarp * 128; wb < E; wb += nwarps * 128) {
        int base = wb + lane * 4;
        int dv[4];
        load_dv4(ei, E, base, is64, dv);
        #pragma unroll
        for (int j = 0; j < 4; j++) {
            int d = dv[j];
            bool match = false;
            #pragma unroll
            for (int t = 0; t < NTGT; t++) match |= (d == tg[t]);
            if (!match) continue;
            int e = base + j;
            int s = load_idx(ei, e, is64);
            float a = __ldg(&ea[e]);
            #pragma unroll
            for (int t = 0; t < NTGT; t++) {
                if (d == tg[t]) {
                    int pos = atomicAdd(&g_ne2, 1);
                    if (pos < MAXE) {
                        g_e2src[pos]  = s;
                        g_e2slot[pos] = t;
                        g_e2a[pos]    = a;
                    }
                }
            }
            unsigned bit = 1u << (s & 31);
            unsigned old = atomicOr(&g_bitmap[s >> 5], bit);
            if (!(old & bit)) {
                int sl = atomicAdd(&g_ns1, 1);
                g_s1[sl] = s;
                zero_agg1_row(s);
            }
        }
    }

    grid_barrier();   // (1) bitmap + agg1-row zeroing complete

    // ---- phase B: S1-bitmap hits -> edge pass 1, warp-cooperative ----
    {
        float2 wv = *((const float2*)We1 + lane);
        float2 bv = *((const float2*)be1 + lane);
        for (int wb = gwarp * 128; wb < E; wb += nwarps * 128) {
            int base = wb + lane * 4;
            int dv[4];
            load_dv4(ei, E, base, is64, dv);
            #pragma unroll
            for (int j = 0; j < 4; j++) {
                int d = dv[j];
                bool hit = (d >= 0) && ((g_bitmap[d >> 5] >> (d & 31)) & 1u);
                unsigned m = __ballot_sync(0xffffffffu, hit);
                while (m) {
                    int src_lane = __ffs(m) - 1;
                    m &= m - 1;
                    int e  = __shfl_sync(0xffffffffu, base + j, src_lane);
                    int dd = __shfl_sync(0xffffffffu, d, src_lane);
                    long long s = is64 ? ((const long long*)ei)[e]
                                       : (long long)((const int*)ei)[e];
                    float a = __ldg(&ea[e]);
                    float2 xv = *((const float2*)(x + s * Hd) + lane);
                    float m0 = fmaxf(xv.x + fmaf(a, wv.x, bv.x), 0.f);
                    float m1 = fmaxf(xv.y + fmaf(a, wv.y, bv.y), 0.f);
                    float* dp = g_agg1 + (size_t)dd * Hd + 2 * lane;
                    asm volatile("red.global.add.v2.f32 [%0], {%1,%2};"
                                 :: "l"(dp), "f"(m0), "f"(m1) : "memory");
                }
            }
        }
    }

    grid_barrier();   // (2) agg1 complete

    int ns1 = g_ns1;

    // ---- phase C: layer-1 MLP at S1 nodes (4 nodes/block) ----
    {
        int nl = tid >> 6;     // 0..3
        int j  = tid & 63;
        for (int nbase = bid * 4; nbase < ns1; nbase += NBLK * 4) {
            int idx = nbase + nl;
            bool valid = (idx < ns1);
            if (valid) {
                size_t node = (size_t)g_s1[idx];
                sIn[tid] = x[node * Hd + j] + g_agg1[node * Hd + j];
            } else sIn[tid] = 0.f;
            __syncthreads();
            {
                float acc = __ldg(&b1a[j]);
                const float* in = &sIn[nl * Hd];
                #pragma unroll 16
                for (int k = 0; k < Hd; k++)
                    acc = fmaf(in[k], __ldg(&W1a[k * Hd + j]), acc);
                sMu[tid] = fmaxf(acc, 0.f);
            }
            __syncthreads();
            {
                float acc = __ldg(&b1b[j]);
                const float* u = &sMu[nl * Hd];
                #pragma unroll 16
                for (int k = 0; k < Hd; k++)
                    acc = fmaf(u[k], __ldg(&W1b[k * Hd + j]), acc);
                if (valid) {
                    size_t node = (size_t)g_s1[idx];
                    g_h1[node * Hd + j] = fmaxf(acc, 0.f);
                }
            }
            __syncthreads();
        }
    }

    grid_barrier();   // (3) h1 complete

    // ---- phase D: conv2 for one target slot per block (blocks 0..nt-1) ----
    if (bid < nt) {
        int slot = bid;
        int tgv = tg[slot];

        if (tid < Hd) sA[tid] = 0.f;
        __syncthreads();

        int count = g_ne2;
        if (count > MAXE) count = MAXE;
        for (int idx = tid; idx < count * 16; idx += 256) {
            int ent = idx >> 4;
            if (g_e2slot[ent] != slot) continue;
            int l = idx & 15;
            int s   = g_e2src[ent];
            float a = g_e2a[ent];
            float4 xv = *((const float4*)(g_h1 + (size_t)s * Hd) + l);
            float4 wv = __ldg((const float4*)We2 + l);
            float4 bv = __ldg((const float4*)be2 + l);
            float* base2 = &sA[l * 4];
            atomicAdd(base2 + 0, fmaxf(xv.x + fmaf(a, wv.x, bv.x), 0.f));
            atomicAdd(base2 + 1, fmaxf(xv.y + fmaf(a, wv.y, bv.y), 0.f));
            atomicAdd(base2 + 2, fmaxf(xv.z + fmaf(a, wv.z, bv.z), 0.f));
            atomicAdd(base2 + 3, fmaxf(xv.w + fmaf(a, wv.w, bv.w), 0.f));
        }
        __syncthreads();

        if (tid < Hd) sA[tid] += g_h1[(size_t)tgv * Hd + tid];
        __syncthreads();

        // mlp2A: 4 threads per output, split-K (depth 16), shfl reduce
        {
            int j   = tid >> 2;
            int sub = tid & 3;
            float acc = 0.f;
            #pragma unroll
            for (int q = 0; q < 16; q++) {
                int k = sub * 16 + q;
                acc = fmaf(sA[k], __ldg(&W2a[k * Hd + j]), acc);
            }
            acc += __shfl_down_sync(0xffffffffu, acc, 2, 4);
            acc += __shfl_down_sync(0xffffffffu, acc, 1, 4);
            if (sub == 0) sU[j] = fmaxf(acc + __ldg(&b2a[j]), 0.f);
        }
        __syncthreads();

        // mlp2B (no relu), write h2 row to global
        {
            int j   = tid >> 2;
            int sub = tid & 3;
            float acc = 0.f;
            #pragma unroll
            for (int q = 0; q < 16; q++) {
                int k = sub * 16 + q;
                acc = fmaf(sU[k], __ldg(&W2b[k * Hd + j]), acc);
            }
            acc += __shfl_down_sync(0xffffffffu, acc, 2, 4);
            acc += __shfl_down_sync(0xffffffffu, acc, 1, 4);
            if (sub == 0) g_h2[slot * Hd + j] = acc + __ldg(&b2b[j]);
        }
    }

    grid_barrier();   // (4) all h2 rows written

    // ---- phase E-a: cleanup on block K (concurrent with head blocks) ----
    if (bid == K) {
        for (int i = tid; i < ns1; i += 256) g_bitmap[g_s1[i] >> 5] = 0u;
        if (tid == 0) { g_ns1 = 0; g_ne2 = 0; }
        return;
    }
    if (bid >= K) return;

    // ---- phase E-b: Q head, one neighbor per block (blocks 0..K-1) ----
    {
        int k = bid;
        if (tid < 2 * Hd) sC[tid] = g_h2[tid];
        else if (tid < 3 * Hd) sC[tid] = g_h2[(2 + k) * Hd + (tid - 2 * Hd)];
        __syncthreads();

        // lin1: 192-deep, 4 threads per output (depth 48), shfl reduce
        {
            int j   = tid >> 2;
            int sub = tid & 3;
            float acc = 0.f;
            #pragma unroll
            for (int q = 0; q < 48; q++) {
                int t = sub * 48 + q;
                acc = fmaf(sC[t], __ldg(&Wl1[t * Hd + j]), acc);
            }
            acc += __shfl_down_sync(0xffffffffu, acc, 2, 4);
            acc += __shfl_down_sync(0xffffffffu, acc, 1, 4);
            if (sub == 0) sZ[j] = fmaxf(acc + __ldg(&bl1[j]), 0.f);
        }
        __syncthreads();

        // lin2: warp 0 does the 64-dot via shuffle
        if (tid < 32) {
            float v = fmaf(sZ[tid], __ldg(&Wl2[tid]), 0.f)
                    + sZ[tid + 32] * __ldg(&Wl2[tid + 32]);
            #pragma unroll
            for (int o = 16; o > 0; o >>= 1)
                v += __shfl_down_sync(0xffffffffu, v, o);
            if (tid == 0) out[k] = v + __ldg(&bl2[0]);
        }
    }
}

// ---------------- launcher ----------------
extern "C" void kernel_launch(void* const* d_in, const int* in_sizes, int n_in,
                              void* d_out, int out_size) {
    const float* x    = (const float*)d_in[0];
    const void*  ei   = d_in[1];
    const void*  curr = d_in[2];
    const void*  dest = d_in[3];
    const void*  nbr  = d_in[4];
    const float* ea   = (const float*)d_in[5];
    const float* We1  = (const float*)d_in[6];
    const float* be1  = (const float*)d_in[7];
    const float* W1a  = (const float*)d_in[8];
    const float* b1a  = (const float*)d_in[9];
    const float* W1b  = (const float*)d_in[10];
    const float* b1b  = (const float*)d_in[11];
    const float* We2  = (const float*)d_in[12];
    const float* be2  = (const float*)d_in[13];
    const float* W2a  = (const float*)d_in[14];
    const float* b2a  = (const float*)d_in[15];
    const float* W2b  = (const float*)d_in[16];
    const float* b2b  = (const float*)d_in[17];
    const float* Wl1  = (const float*)d_in[18];
    const float* bl1  = (const float*)d_in[19];
    const float* Wl2  = (const float*)d_in[20];
    const float* bl2  = (const float*)d_in[21];

    int N = in_sizes[0] / Hd;
    int E = in_sizes[5];
    int K = in_sizes[4];
    if (K > MAXK) K = MAXK;

    k_all<<<NBLK, 256>>>(x, ei, ea, curr, dest, nbr,
                         We1, be1, W1a, b1a, W1b, b1b,
                         We2, be2, W2a, b2a, W2b, b2b,
                         Wl1, bl1, Wl2, bl2,
                         (float*)d_out, E, (long long)N, K);
}